// round 2
// baseline (speedup 1.0000x reference)
#include <cuda_runtime.h>
#include <cuda_bf16.h>

typedef unsigned long long u64;

#define Bq   8192
#define Tq   28
#define Iq   28
#define Hq   128
#define Cq   10
#define BT   64        // batch rows per CTA (main kernel)
#define HTS  64        // transposed h row stride (= BT)

// ------------------------- device scratch (static, no allocation) -------------------------
__device__ float g_xw0[(size_t)Bq * Tq * Hq];   // x @ W_ih0^T + b_ih0 + b_hh0, row = b*T+t
__device__ float g_w0t[Hq * Hq];                // W_hh0^T : [k][j]
__device__ float g_w1t[2 * Hq * Hq];            // [0:128)=W_ih1^T, [128:256)=W_hh1^T, [k][j]
__device__ float g_b1[Hq];                      // b_ih1 + b_hh1

// ------------------------- packed f32x2 helpers -------------------------
static __device__ __forceinline__ u64 pack2(float v) {
    u64 r; asm("mov.b64 %0, {%1, %1};" : "=l"(r) : "f"(v)); return r;
}
static __device__ __forceinline__ u64 pack22(float a, float b) {
    u64 r; asm("mov.b64 %0, {%1, %2};" : "=l"(r) : "f"(a), "f"(b)); return r;
}
static __device__ __forceinline__ void unpack2(u64 v, float& lo, float& hi) {
    asm("mov.b64 {%0, %1}, %2;" : "=f"(lo), "=f"(hi) : "l"(v));
}
static __device__ __forceinline__ void ffma2(u64& d, u64 a, u64 b) {
    asm("fma.rn.f32x2 %0, %1, %2, %0;" : "+l"(d) : "l"(a), "l"(b));
}
static __device__ __forceinline__ float tanh_fast(float x) {
    float ax = fabsf(x);
    float e  = __expf(-2.0f * ax);
    float r  = __fdividef(1.0f - e, 1.0f + e);
    return copysignf(r, x);
}

// ------------------------- core register-tile GEMM -------------------------
// acc[4][4] : 4 rows x 8 cols (as 4 f32x2 col-pairs). hT is transposed input
// [k][row] with row-stride HTSTR, already offset to this thread's r0.
// Wt is K-major [k][128] (shared or global).
template<int KLEN, int HTSTR>
static __device__ __forceinline__ void gemm_tile(u64 acc[4][4], const float* hT,
                                                 const float* Wt, int j0)
{
    #pragma unroll 4
    for (int k = 0; k < KLEN; k++) {
        float4 h4 = *(const float4*)(hT + (size_t)k * HTSTR);  // 4 rows at this k
        const ulonglong2* wp = (const ulonglong2*)(Wt + (size_t)k * Hq + j0);
        ulonglong2 wa = wp[0];   // cols j0..j0+3
        ulonglong2 wb = wp[1];   // cols j0+4..j0+7
        u64 h0 = pack2(h4.x), h1 = pack2(h4.y), h2 = pack2(h4.z), h3 = pack2(h4.w);
        ffma2(acc[0][0], h0, wa.x); ffma2(acc[0][1], h0, wa.y);
        ffma2(acc[0][2], h0, wb.x); ffma2(acc[0][3], h0, wb.y);
        ffma2(acc[1][0], h1, wa.x); ffma2(acc[1][1], h1, wa.y);
        ffma2(acc[1][2], h1, wb.x); ffma2(acc[1][3], h1, wb.y);
        ffma2(acc[2][0], h2, wa.x); ffma2(acc[2][1], h2, wa.y);
        ffma2(acc[2][2], h2, wb.x); ffma2(acc[2][3], h2, wb.y);
        ffma2(acc[3][0], h3, wa.x); ffma2(acc[3][1], h3, wa.y);
        ffma2(acc[3][2], h3, wb.x); ffma2(acc[3][3], h3, wb.y);
    }
}

// ------------------------- kernel 1: transpose weights, fuse biases -------------------------
__global__ void __launch_bounds__(256) prep_kernel(
    const float* __restrict__ Whh0, const float* __restrict__ Wih1,
    const float* __restrict__ Whh1, const float* __restrict__ bih1,
    const float* __restrict__ bhh1)
{
    int idx = blockIdx.x * 256 + threadIdx.x;     // idx = k*128 + j
    int k = idx >> 7, j = idx & 127;
    g_w0t[idx]            = Whh0[j * Hq + k];
    g_w1t[idx]            = Wih1[j * Hq + k];
    g_w1t[Hq * Hq + idx]  = Whh1[j * Hq + k];
    if (idx < Hq) g_b1[idx] = bih1[idx] + bhh1[idx];
}

// ------------------------- kernel 2: xw0 = x @ W_ih0^T + (b_ih0 + b_hh0) -------------------------
__global__ void __launch_bounds__(256) xw_kernel(
    const float* __restrict__ x, const float* __restrict__ Wih0,
    const float* __restrict__ bih0, const float* __restrict__ bhh0)
{
    __shared__ float sxT[Iq * 64];     // [d][row], stride 64
    __shared__ float sW[Iq * Hq];      // [d][j]
    const int tid = threadIdx.x;
    const int ty = tid & 15, tx = tid >> 4;
    const int r0 = ty * 4, j0 = tx * 8;
    const size_t base = (size_t)blockIdx.x * 64;   // flattened row b*T+t

    for (int i = tid; i < Iq * Hq; i += 256) {     // conflict-free smem writes
        int d = i >> 7, j = i & 127;
        sW[i] = Wih0[j * Iq + d];
    }
    for (int i = tid; i < Iq * 64; i += 256) {
        int d = i >> 6, row = i & 63;
        sxT[i] = x[(base + row) * Iq + d];
    }

    u64 acc[4][4];
    {
        float bv[8];
        #pragma unroll
        for (int c = 0; c < 8; c++) bv[c] = bih0[j0 + c] + bhh0[j0 + c];
        #pragma unroll
        for (int rr = 0; rr < 4; rr++) {
            acc[rr][0] = pack22(bv[0], bv[1]); acc[rr][1] = pack22(bv[2], bv[3]);
            acc[rr][2] = pack22(bv[4], bv[5]); acc[rr][3] = pack22(bv[6], bv[7]);
        }
    }
    __syncthreads();

    gemm_tile<Iq, 64>(acc, sxT + r0, sW, j0);

    #pragma unroll
    for (int rr = 0; rr < 4; rr++) {
        float o[8];
        unpack2(acc[rr][0], o[0], o[1]); unpack2(acc[rr][1], o[2], o[3]);
        unpack2(acc[rr][2], o[4], o[5]); unpack2(acc[rr][3], o[6], o[7]);
        float* p = &g_xw0[(base + r0 + rr) * Hq + j0];
        *(float4*)(p)     = make_float4(o[0], o[1], o[2], o[3]);
        *(float4*)(p + 4) = make_float4(o[4], o[5], o[6], o[7]);
    }
}

// ------------------------- kernel 3: fused 2-layer recurrence + FC -------------------------
__global__ void __launch_bounds__(256, 1) rnn_main(
    const float* __restrict__ fc_w, const float* __restrict__ fc_b,
    float* __restrict__ out)
{
    extern __shared__ float smem[];
    float* sh0 = smem;                 // [128][64] transposed h0
    float* sh1 = smem + Hq * HTS;      // [128][64] transposed h1

    const int tid = threadIdx.x;
    const int ty = tid & 15, tx = tid >> 4;
    const int r0 = ty * 4, j0 = tx * 8;
    const size_t b0 = (size_t)blockIdx.x * BT;

    for (int i = tid; i < Hq * HTS; i += 256) { sh0[i] = 0.0f; sh1[i] = 0.0f; }

    u64 b1p[4];
    {
        float4 ba = *(const float4*)&g_b1[j0];
        float4 bb = *(const float4*)&g_b1[j0 + 4];
        b1p[0] = pack22(ba.x, ba.y); b1p[1] = pack22(ba.z, ba.w);
        b1p[2] = pack22(bb.x, bb.y); b1p[3] = pack22(bb.z, bb.w);
    }
    __syncthreads();

    for (int t = 0; t < Tq; t++) {
        // ---- layer 0: acc = xw0[:, t] + h0 @ W_hh0^T ----
        u64 acc[4][4];
        #pragma unroll
        for (int rr = 0; rr < 4; rr++) {
            const float* p = &g_xw0[((b0 + r0 + rr) * Tq + t) * Hq + j0];
            float4 a = *(const float4*)(p);
            float4 b = *(const float4*)(p + 4);
            acc[rr][0] = pack22(a.x, a.y); acc[rr][1] = pack22(a.z, a.w);
            acc[rr][2] = pack22(b.x, b.y); acc[rr][3] = pack22(b.z, b.w);
        }
        gemm_tile<Hq, HTS>(acc, sh0 + r0, g_w0t, j0);

        float vt[4][8];
        #pragma unroll
        for (int rr = 0; rr < 4; rr++) {
            #pragma unroll
            for (int cc = 0; cc < 4; cc++) {
                float a, b; unpack2(acc[rr][cc], a, b);
                vt[rr][2 * cc]     = tanh_fast(a);
                vt[rr][2 * cc + 1] = tanh_fast(b);
            }
        }
        __syncthreads();                      // everyone done reading old h0
        #pragma unroll
        for (int c = 0; c < 8; c++)
            *(float4*)&sh0[(size_t)(j0 + c) * HTS + r0] =
                make_float4(vt[0][c], vt[1][c], vt[2][c], vt[3][c]);
        __syncthreads();                      // new h0 visible

        // ---- layer 1: acc1 = b1 + h0_new @ W_ih1^T + h1 @ W_hh1^T ----
        u64 acc1[4][4];
        #pragma unroll
        for (int rr = 0; rr < 4; rr++) {
            acc1[rr][0] = b1p[0]; acc1[rr][1] = b1p[1];
            acc1[rr][2] = b1p[2]; acc1[rr][3] = b1p[3];
        }
        gemm_tile<Hq, HTS>(acc1, sh0 + r0, g_w1t, j0);
        gemm_tile<Hq, HTS>(acc1, sh1 + r0, g_w1t + Hq * Hq, j0);

        #pragma unroll
        for (int rr = 0; rr < 4; rr++) {
            #pragma unroll
            for (int cc = 0; cc < 4; cc++) {
                float a, b; unpack2(acc1[rr][cc], a, b);
                vt[rr][2 * cc]     = tanh_fast(a);
                vt[rr][2 * cc + 1] = tanh_fast(b);
            }
        }
        __syncthreads();                      // everyone done reading old h1
        #pragma unroll
        for (int c = 0; c < 8; c++)
            *(float4*)&sh1[(size_t)(j0 + c) * HTS + r0] =
                make_float4(vt[0][c], vt[1][c], vt[2][c], vt[3][c]);
        __syncthreads();                      // new h1 visible
    }

    // ---- FC epilogue: out[b, c] = h1[b] . fc_w[c] + fc_b[c] ----
    for (int idx = tid; idx < BT * Cq; idx += 256) {
        int r = idx / Cq, c = idx - r * Cq;
        float s = fc_b[c];
        #pragma unroll 4
        for (int k = 0; k < Hq; k++)
            s += sh1[(size_t)k * HTS + r] * __ldg(&fc_w[c * Hq + k]);
        out[(b0 + r) * Cq + c] = s;
    }
}

// ------------------------- host entry -------------------------
extern "C" void kernel_launch(void* const* d_in, const int* in_sizes, int n_in,
                              void* d_out, int out_size) {
    const float* x     = (const float*)d_in[0];
    const float* W_ih0 = (const float*)d_in[1];
    const float* W_hh0 = (const float*)d_in[2];
    const float* b_ih0 = (const float*)d_in[3];
    const float* b_hh0 = (const float*)d_in[4];
    const float* W_ih1 = (const float*)d_in[5];
    const float* W_hh1 = (const float*)d_in[6];
    const float* b_ih1 = (const float*)d_in[7];
    const float* b_hh1 = (const float*)d_in[8];
    const float* fc_w  = (const float*)d_in[9];
    const float* fc_b  = (const float*)d_in[10];
    float* out = (float*)d_out;

    const int smem_main = 2 * Hq * HTS * (int)sizeof(float);   // 64 KB
    cudaFuncSetAttribute(rnn_main, cudaFuncAttributeMaxDynamicSharedMemorySize, smem_main);

    prep_kernel<<<(Hq * Hq) / 256, 256>>>(W_hh0, W_ih1, W_hh1, b_ih1, b_hh1);
    xw_kernel<<<(Bq * Tq) / 64, 256>>>(x, W_ih0, b_ih0, b_hh0);
    rnn_main<<<Bq / BT, 256, smem_main>>>(fc_w, fc_b, out);
}

// round 6
// speedup vs baseline: 2.7718x; 2.7718x over previous
#include <cuda_runtime.h>
#include <cuda_bf16.h>
#include <cstdint>

typedef unsigned int u32;

#define Bq 8192
#define Tq 28
#define Iq 28
#define Hq 128
#define Cq 10

// ---------------- device scratch ----------------
// xw0 in mma-fragment layout: [t][gw(512)][nt(16)][lane(32)][q(4)] floats
__device__ float g_xw0[(size_t)Tq * 512 * 16 * 32 * 4];

// ---------------- helpers ----------------
static __device__ __forceinline__ u32 smem_u32(const void* p) {
    u32 a; asm("{ .reg .u64 t; cvta.to.shared.u64 t, %1; cvt.u32.u64 %0, t; }" : "=r"(a) : "l"(p));
    return a;
}
static __device__ __forceinline__ float tanh_fast(float x) {
    float ax = fabsf(x);
    float e  = __expf(-2.0f * ax);
    float r  = __fdividef(1.0f - e, 1.0f + e);
    return copysignf(r, x);
}
// pack {lo_elem, hi_elem} -> b32 (lo in low 16 bits)
static __device__ __forceinline__ u32 pack_bf16x2(float lo, float hi) {
    u32 r; asm("cvt.rn.bf16x2.f32 %0, %1, %2;" : "=r"(r) : "f"(hi), "f"(lo));
    return r;
}
static __device__ __forceinline__ float lo16f(u32 p) { return __uint_as_float(p << 16); }
static __device__ __forceinline__ float hi16f(u32 p) { return __uint_as_float(p & 0xFFFF0000u); }

static __device__ __forceinline__ void mma_bf16(float (&d)[4], const u32 (&a)[4], u32 b0, u32 b1) {
    asm volatile(
        "mma.sync.aligned.m16n8k16.row.col.f32.bf16.bf16.f32 "
        "{%0,%1,%2,%3}, {%4,%5,%6,%7}, {%8,%9}, {%0,%1,%2,%3};"
        : "+f"(d[0]), "+f"(d[1]), "+f"(d[2]), "+f"(d[3])
        : "r"(a[0]), "r"(a[1]), "r"(a[2]), "r"(a[3]), "r"(b0), "r"(b1));
}
#define LDMX4(r0, r1, r2, r3, addr) \
    asm volatile("ldmatrix.sync.aligned.m8n8.x4.shared.b16 {%0,%1,%2,%3}, [%4];" \
        : "=r"(r0), "=r"(r1), "=r"(r2), "=r"(r3) : "r"(addr))

// W smem tile: [j 0..127][k 0..127] bf16, row stride 272 bytes (conflict-free ldmatrix)
#define WROW 272
#define WTILE 34816          // 128 * 272

// 3-term emulated-fp32 GEMM: D[16 nt][4] += A(hi,lo) @ W(hi,lo)^T
// Each LDMX4 covers 16 j-rows: matrices 0/1 = j..j+7 (k lo/hi), 2/3 = j+8..j+15.
static __device__ __forceinline__ void gemm3(float (&D)[16][4],
                                             const u32 (&Ah)[8][4], const u32 (&Al)[8][4],
                                             u32 wh, u32 wl, u32 lmrow)
{
    #pragma unroll
    for (int kt = 0; kt < 8; kt++) {
        #pragma unroll
        for (int np = 0; np < 8; np++) {
            u32 bh0, bh1, bh2, bh3, bl0, bl1, bl2, bl3;
            u32 off = (u32)(np * 16 * WROW + kt * 32) + lmrow;   // FIXED: 16-row stride
            LDMX4(bh0, bh1, bh2, bh3, wh + off);
            LDMX4(bl0, bl1, bl2, bl3, wl + off);
            mma_bf16(D[2 * np],     Ah[kt], bh0, bh1);
            mma_bf16(D[2 * np],     Al[kt], bh0, bh1);
            mma_bf16(D[2 * np],     Ah[kt], bl0, bl1);
            mma_bf16(D[2 * np + 1], Ah[kt], bh2, bh3);
            mma_bf16(D[2 * np + 1], Al[kt], bh2, bh3);
            mma_bf16(D[2 * np + 1], Ah[kt], bl2, bl3);
        }
    }
}

// ================= f32x2 helpers (xw kernel) =================
typedef unsigned long long u64;
static __device__ __forceinline__ u64 pack2(float v) {
    u64 r; asm("mov.b64 %0, {%1, %1};" : "=l"(r) : "f"(v)); return r;
}
static __device__ __forceinline__ u64 pack22(float a, float b) {
    u64 r; asm("mov.b64 %0, {%1, %2};" : "=l"(r) : "f"(a), "f"(b)); return r;
}
static __device__ __forceinline__ void unpack2(u64 v, float& lo, float& hi) {
    asm("mov.b64 {%0, %1}, %2;" : "=f"(lo), "=f"(hi) : "l"(v));
}
static __device__ __forceinline__ void ffma2(u64& d, u64 a, u64 b) {
    asm("fma.rn.f32x2 %0, %1, %2, %0;" : "+l"(d) : "l"(a), "l"(b));
}

// ================= kernel 1: xw0 = x @ W_ih0^T + (b_ih0+b_hh0), frag layout =================
__global__ void __launch_bounds__(256) xw_kernel(
    const float* __restrict__ x, const float* __restrict__ Wih0,
    const float* __restrict__ bih0, const float* __restrict__ bhh0)
{
    __shared__ float sxT[Iq * 64];       // [d][row]
    __shared__ float sW[Iq * Hq];        // [d][j]
    __shared__ float sxw[64 * 132];      // [row][j] padded

    const int tid = threadIdx.x;
    const int t = blockIdx.x >> 7;       // 0..27
    const int bblk = blockIdx.x & 127;   // 0..127
    const size_t b0 = (size_t)bblk * 64;

    for (int i = tid; i < Iq * Hq; i += 256) {
        int j = i / Iq, d = i - j * Iq;
        sW[d * Hq + j] = Wih0[i];
    }
    for (int i = tid; i < Iq * 64; i += 256) {
        int row = i / Iq, d = i - row * Iq;
        sxT[d * 64 + row] = x[((b0 + row) * Tq + t) * Iq + d];
    }
    __syncthreads();

    const int ty = tid & 15, tx = tid >> 4;
    const int r0 = ty * 4, j0 = tx * 8;

    u64 acc[4][4];
    {
        float bv[8];
        #pragma unroll
        for (int c = 0; c < 8; c++) bv[c] = bih0[j0 + c] + bhh0[j0 + c];
        #pragma unroll
        for (int rr = 0; rr < 4; rr++) {
            acc[rr][0] = pack22(bv[0], bv[1]); acc[rr][1] = pack22(bv[2], bv[3]);
            acc[rr][2] = pack22(bv[4], bv[5]); acc[rr][3] = pack22(bv[6], bv[7]);
        }
    }

    #pragma unroll 4
    for (int k = 0; k < Iq; k++) {
        float4 h4 = *(const float4*)(sxT + k * 64 + r0);
        const ulonglong2* wp = (const ulonglong2*)(sW + k * Hq + j0);
        ulonglong2 wa = wp[0], wb = wp[1];
        u64 h0 = pack2(h4.x), h1 = pack2(h4.y), h2 = pack2(h4.z), h3 = pack2(h4.w);
        ffma2(acc[0][0], h0, wa.x); ffma2(acc[0][1], h0, wa.y);
        ffma2(acc[0][2], h0, wb.x); ffma2(acc[0][3], h0, wb.y);
        ffma2(acc[1][0], h1, wa.x); ffma2(acc[1][1], h1, wa.y);
        ffma2(acc[1][2], h1, wb.x); ffma2(acc[1][3], h1, wb.y);
        ffma2(acc[2][0], h2, wa.x); ffma2(acc[2][1], h2, wa.y);
        ffma2(acc[2][2], h2, wb.x); ffma2(acc[2][3], h2, wb.y);
        ffma2(acc[3][0], h3, wa.x); ffma2(acc[3][1], h3, wa.y);
        ffma2(acc[3][2], h3, wb.x); ffma2(acc[3][3], h3, wb.y);
    }

    #pragma unroll
    for (int rr = 0; rr < 4; rr++) {
        float o[8];
        unpack2(acc[rr][0], o[0], o[1]); unpack2(acc[rr][1], o[2], o[3]);
        unpack2(acc[rr][2], o[4], o[5]); unpack2(acc[rr][3], o[6], o[7]);
        float* p = &sxw[(r0 + rr) * 132 + j0];
        *(float4*)(p)     = make_float4(o[0], o[1], o[2], o[3]);
        *(float4*)(p + 4) = make_float4(o[4], o[5], o[6], o[7]);
    }
    __syncthreads();

    // remap to fragment layout, coalesced float4 stores
    float4* dst = (float4*)g_xw0;
    for (int w = tid; w < 2048; w += 256) {
        int gwp = w >> 9, nt = (w >> 5) & 15, lane = w & 31;
        int g = lane >> 2, p = lane & 3;
        int c0 = nt * 8 + p * 2;
        int ra = gwp * 16 + g, rb = ra + 8;
        float4 o = make_float4(sxw[ra * 132 + c0], sxw[ra * 132 + c0 + 1],
                               sxw[rb * 132 + c0], sxw[rb * 132 + c0 + 1]);
        size_t gw = (size_t)bblk * 4 + gwp;
        dst[(((size_t)t * 512 + gw) * 16 + nt) * 32 + lane] = o;
    }
}

// ================= kernel 2: fused 2-layer recurrence (HMMA) + FC =================
// dyn smem layout (bytes):
//   0                : 6 W tiles (order: W0h, W0l, Wih1h, Wih1l, Whh1h, Whh1l), 6*34816
//   208896           : b1 frag  float2[16][32]
//   212992           : fcw      float[10][128]
//   218112           : fcb      float[10]
#define OFF_B1F 208896
#define OFF_FCW 212992
#define OFF_FCB 218112
#define SMEM_DYN 218624

__global__ void __launch_bounds__(128, 1) rnn_main(
    const float* __restrict__ W_hh0, const float* __restrict__ W_ih1,
    const float* __restrict__ W_hh1, const float* __restrict__ b_ih1,
    const float* __restrict__ b_hh1, const float* __restrict__ fc_w,
    const float* __restrict__ fc_b, float* __restrict__ out)
{
    extern __shared__ char dyn[];
    const int tid = threadIdx.x;
    const int wid = tid >> 5, lane = tid & 31;
    const size_t gw = (size_t)blockIdx.x * 4 + wid;

    // ---- fill W tiles (fp32 -> bf16 hi/lo, padded rows) ----
    {
        const float* Ws[3] = { W_hh0, W_ih1, W_hh1 };
        #pragma unroll
        for (int m = 0; m < 3; m++) {
            __nv_bfloat16* dh = (__nv_bfloat16*)(dyn + (2 * m) * WTILE);
            __nv_bfloat16* dl = (__nv_bfloat16*)(dyn + (2 * m + 1) * WTILE);
            const float* W = Ws[m];
            for (int i = tid; i < Hq * Hq; i += 128) {
                int j = i >> 7, k = i & 127;
                float v = W[i];
                __nv_bfloat16 hb = __float2bfloat16(v);
                float lf = v - __bfloat162float(hb);
                dh[j * 136 + k] = hb;
                dl[j * 136 + k] = __float2bfloat16(lf);
            }
        }
    }
    float2* b1f = (float2*)(dyn + OFF_B1F);
    float*  fcw = (float*)(dyn + OFF_FCW);
    float*  fcb = (float*)(dyn + OFF_FCB);
    for (int i = tid; i < 512; i += 128) {
        int nt = i >> 5, l = i & 31, p = l & 3, j = nt * 8 + 2 * p;
        b1f[i] = make_float2(b_ih1[j] + b_hh1[j], b_ih1[j + 1] + b_hh1[j + 1]);
    }
    for (int i = tid; i < Cq * Hq; i += 128) fcw[i] = fc_w[i];
    if (tid < Cq) fcb[tid] = fc_b[tid];
    __syncthreads();

    const u32 smb = smem_u32(dyn);
    const u32 lmrow = (u32)(((((lane >> 4) & 1) * 8 + (lane & 7)) * WROW) + (((lane >> 3) & 1) * 16));
    const u32 W0H = smb,              W0L = smb + WTILE;
    const u32 WIH = smb + 2 * WTILE,  WIL = smb + 3 * WTILE;
    const u32 WHH = smb + 4 * WTILE,  WHL = smb + 5 * WTILE;

    u32 h0h[8][4], h0l[8][4], h1h[8][4], h1l[8][4];
    float D[16][4];

    const float4* xsrc = (const float4*)g_xw0;

    for (int t = 0; t < Tq; t++) {
        // ---- D init from xw frags (coalesced) ----
        {
            const float4* xp = xsrc + (((size_t)t * 512 + gw) * 16) * 32 + lane;
            #pragma unroll
            for (int nt = 0; nt < 16; nt++) {
                float4 v = xp[nt * 32];
                D[nt][0] = v.x; D[nt][1] = v.y; D[nt][2] = v.z; D[nt][3] = v.w;
            }
        }
        if (t > 0) gemm3(D, h0h, h0l, W0H, W0L, lmrow);

        // ---- epilogue 0 -> h0 frags ----
        #pragma unroll
        for (int kt = 0; kt < 8; kt++) {
            #pragma unroll
            for (int o = 0; o < 2; o++) {
                int nt = 2 * kt + o;
                float v0 = tanh_fast(D[nt][0]);
                float v1 = tanh_fast(D[nt][1]);
                float v2 = tanh_fast(D[nt][2]);
                float v3 = tanh_fast(D[nt][3]);
                u32 p01 = pack_bf16x2(v0, v1);
                u32 p23 = pack_bf16x2(v2, v3);
                h0h[kt][2 * o]     = p01;
                h0h[kt][2 * o + 1] = p23;
                h0l[kt][2 * o]     = pack_bf16x2(v0 - lo16f(p01), v1 - hi16f(p01));
                h0l[kt][2 * o + 1] = pack_bf16x2(v2 - lo16f(p23), v3 - hi16f(p23));
            }
        }

        // ---- layer 1: D = b1 + h1@Whh1^T + h0@Wih1^T ----
        #pragma unroll
        for (int nt = 0; nt < 16; nt++) {
            float2 bv = b1f[nt * 32 + lane];
            D[nt][0] = bv.x; D[nt][1] = bv.y; D[nt][2] = bv.x; D[nt][3] = bv.y;
        }
        if (t > 0) gemm3(D, h1h, h1l, WHH, WHL, lmrow);
        gemm3(D, h0h, h0l, WIH, WIL, lmrow);

        // ---- epilogue 1 -> h1 frags (last step keeps tanh'd values in D) ----
        if (t < Tq - 1) {
            #pragma unroll
            for (int kt = 0; kt < 8; kt++) {
                #pragma unroll
                for (int o = 0; o < 2; o++) {
                    int nt = 2 * kt + o;
                    float v0 = tanh_fast(D[nt][0]);
                    float v1 = tanh_fast(D[nt][1]);
                    float v2 = tanh_fast(D[nt][2]);
                    float v3 = tanh_fast(D[nt][3]);
                    u32 p01 = pack_bf16x2(v0, v1);
                    u32 p23 = pack_bf16x2(v2, v3);
                    h1h[kt][2 * o]     = p01;
                    h1h[kt][2 * o + 1] = p23;
                    h1l[kt][2 * o]     = pack_bf16x2(v0 - lo16f(p01), v1 - hi16f(p01));
                    h1l[kt][2 * o + 1] = pack_bf16x2(v2 - lo16f(p23), v3 - hi16f(p23));
                }
            }
        } else {
            #pragma unroll
            for (int nt = 0; nt < 16; nt++) {
                #pragma unroll
                for (int q = 0; q < 4; q++) D[nt][q] = tanh_fast(D[nt][q]);
            }
        }
    }

    // ---- FC epilogue ----
    __syncthreads();                    // W tiles no longer needed by anyone
    float* stg = (float*)(dyn + wid * 8448);   // [16 rows][132] per warp
    {
        int g = lane >> 2, p = lane & 3;
        #pragma unroll
        for (int nt = 0; nt < 16; nt++) {
            int j = nt * 8 + p * 2;
            stg[g * 132 + j]           = D[nt][0];
            stg[g * 132 + j + 1]       = D[nt][1];
            stg[(g + 8) * 132 + j]     = D[nt][2];
            stg[(g + 8) * 132 + j + 1] = D[nt][3];
        }
    }
    __syncwarp();
    {
        int row = lane & 15, half = lane >> 4;
        float acc[Cq];
        #pragma unroll
        for (int c = 0; c < Cq; c++) acc[c] = half ? 0.0f : fcb[c];
        const float* hv = stg + row * 132 + half * 64;
        const float* fw = fcw + half * 64;
        #pragma unroll 4
        for (int k = 0; k < 64; k++) {
            float h = hv[k];
            #pragma unroll
            for (int c = 0; c < Cq; c++)
                acc[c] = fmaf(h, fw[c * Hq + k], acc[c]);
        }
        #pragma unroll
        for (int c = 0; c < Cq; c++) acc[c] += __shfl_xor_sync(0xFFFFFFFFu, acc[c], 16);
        if (lane < 16) {
            size_t b = gw * 16 + row;
            #pragma unroll
            for (int c = 0; c < Cq; c++) out[b * Cq + c] = acc[c];
        }
    }
}

// ================= host entry =================
extern "C" void kernel_launch(void* const* d_in, const int* in_sizes, int n_in,
                              void* d_out, int out_size) {
    const float* x     = (const float*)d_in[0];
    const float* W_ih0 = (const float*)d_in[1];
    const float* W_hh0 = (const float*)d_in[2];
    const float* b_ih0 = (const float*)d_in[3];
    const float* b_hh0 = (const float*)d_in[4];
    const float* W_ih1 = (const float*)d_in[5];
    const float* W_hh1 = (const float*)d_in[6];
    const float* b_ih1 = (const float*)d_in[7];
    const float* b_hh1 = (const float*)d_in[8];
    const float* fc_w  = (const float*)d_in[9];
    const float* fc_b  = (const float*)d_in[10];
    float* out = (float*)d_out;

    cudaFuncSetAttribute(rnn_main, cudaFuncAttributeMaxDynamicSharedMemorySize, SMEM_DYN);

    xw_kernel<<<Tq * 128, 256>>>(x, W_ih0, b_ih0, b_hh0);
    rnn_main<<<128, 128, SMEM_DYN>>>(W_hh0, W_ih1, W_hh1, b_ih1, b_hh1, fc_w, fc_b, out);
}

// round 8
// speedup vs baseline: 2.7733x; 1.0005x over previous
#include <cuda_runtime.h>
#include <cuda_bf16.h>
#include <cstdint>

typedef unsigned int u32;

#define Bq 8192
#define Tq 28
#define Iq 28
#define Hq 128
#define Cq 10

// ---------------- device scratch ----------------
// xw0 in mma-fragment layout: [t][gw(512)][nt(16)][lane(32)][q(4)] floats
__device__ float g_xw0[(size_t)Tq * 512 * 16 * 32 * 4];

// ---------------- helpers ----------------
static __device__ __forceinline__ u32 smem_u32(const void* p) {
    u32 a; asm("{ .reg .u64 t; cvta.to.shared.u64 t, %1; cvt.u32.u64 %0, t; }" : "=r"(a) : "l"(p));
    return a;
}
static __device__ __forceinline__ float tanh_fast(float x) {
    float ax = fabsf(x);
    float e  = __expf(-2.0f * ax);
    float r  = __fdividef(1.0f - e, 1.0f + e);
    return copysignf(r, x);
}
// pack {lo_elem, hi_elem} -> b32 (lo in low 16 bits)
static __device__ __forceinline__ u32 pack_bf16x2(float lo, float hi) {
    u32 r; asm("cvt.rn.bf16x2.f32 %0, %1, %2;" : "=r"(r) : "f"(hi), "f"(lo));
    return r;
}
static __device__ __forceinline__ float lo16f(u32 p) { return __uint_as_float(p << 16); }
static __device__ __forceinline__ float hi16f(u32 p) { return __uint_as_float(p & 0xFFFF0000u); }

static __device__ __forceinline__ void mma_bf16(float (&d)[4], const u32 (&a)[4], u32 b0, u32 b1) {
    asm volatile(
        "mma.sync.aligned.m16n8k16.row.col.f32.bf16.bf16.f32 "
        "{%0,%1,%2,%3}, {%4,%5,%6,%7}, {%8,%9}, {%0,%1,%2,%3};"
        : "+f"(d[0]), "+f"(d[1]), "+f"(d[2]), "+f"(d[3])
        : "r"(a[0]), "r"(a[1]), "r"(a[2]), "r"(a[3]), "r"(b0), "r"(b1));
}
#define LDMX4(r0, r1, r2, r3, addr) \
    asm volatile("ldmatrix.sync.aligned.m8n8.x4.shared.b16 {%0,%1,%2,%3}, [%4];" \
        : "=r"(r0), "=r"(r1), "=r"(r2), "=r"(r3) : "r"(addr))

// W smem tile: [j 0..127][k 0..127] bf16, row stride 272 bytes (conflict-free ldmatrix)
#define WROW 272
#define WTILE 34816          // 128 * 272

// 3-term emulated-fp32 GEMM: D[16 nt][4] += A(hi,lo) @ W(hi,lo)^T
// Each LDMX4 covers 16 j-rows: matrices 0/1 = j..j+7 (k lo/hi), 2/3 = j+8..j+15.
static __device__ __forceinline__ void gemm3(float (&D)[16][4],
                                             const u32 (&Ah)[8][4], const u32 (&Al)[8][4],
                                             u32 wh, u32 wl, u32 lmrow)
{
    #pragma unroll
    for (int kt = 0; kt < 8; kt++) {
        #pragma unroll
        for (int np = 0; np < 8; np++) {
            u32 bh0, bh1, bh2, bh3, bl0, bl1, bl2, bl3;
            u32 off = (u32)(np * 16 * WROW + kt * 32) + lmrow;   // FIXED: 16-row stride
            LDMX4(bh0, bh1, bh2, bh3, wh + off);
            LDMX4(bl0, bl1, bl2, bl3, wl + off);
            mma_bf16(D[2 * np],     Ah[kt], bh0, bh1);
            mma_bf16(D[2 * np],     Al[kt], bh0, bh1);
            mma_bf16(D[2 * np],     Ah[kt], bl0, bl1);
            mma_bf16(D[2 * np + 1], Ah[kt], bh2, bh3);
            mma_bf16(D[2 * np + 1], Al[kt], bh2, bh3);
            mma_bf16(D[2 * np + 1], Ah[kt], bl2, bl3);
        }
    }
}

// ================= f32x2 helpers (xw kernel) =================
typedef unsigned long long u64;
static __device__ __forceinline__ u64 pack2(float v) {
    u64 r; asm("mov.b64 %0, {%1, %1};" : "=l"(r) : "f"(v)); return r;
}
static __device__ __forceinline__ u64 pack22(float a, float b) {
    u64 r; asm("mov.b64 %0, {%1, %2};" : "=l"(r) : "f"(a), "f"(b)); return r;
}
static __device__ __forceinline__ void unpack2(u64 v, float& lo, float& hi) {
    asm("mov.b64 {%0, %1}, %2;" : "=f"(lo), "=f"(hi) : "l"(v));
}
static __device__ __forceinline__ void ffma2(u64& d, u64 a, u64 b) {
    asm("fma.rn.f32x2 %0, %1, %2, %0;" : "+l"(d) : "l"(a), "l"(b));
}

// ================= kernel 1: xw0 = x @ W_ih0^T + (b_ih0+b_hh0), frag layout =================
__global__ void __launch_bounds__(256) xw_kernel(
    const float* __restrict__ x, const float* __restrict__ Wih0,
    const float* __restrict__ bih0, const float* __restrict__ bhh0)
{
    __shared__ float sxT[Iq * 64];       // [d][row]
    __shared__ float sW[Iq * Hq];        // [d][j]
    __shared__ float sxw[64 * 132];      // [row][j] padded

    const int tid = threadIdx.x;
    const int t = blockIdx.x >> 7;       // 0..27
    const int bblk = blockIdx.x & 127;   // 0..127
    const size_t b0 = (size_t)bblk * 64;

    for (int i = tid; i < Iq * Hq; i += 256) {
        int j = i / Iq, d = i - j * Iq;
        sW[d * Hq + j] = Wih0[i];
    }
    for (int i = tid; i < Iq * 64; i += 256) {
        int row = i / Iq, d = i - row * Iq;
        sxT[d * 64 + row] = x[((b0 + row) * Tq + t) * Iq + d];
    }
    __syncthreads();

    const int ty = tid & 15, tx = tid >> 4;
    const int r0 = ty * 4, j0 = tx * 8;

    u64 acc[4][4];
    {
        float bv[8];
        #pragma unroll
        for (int c = 0; c < 8; c++) bv[c] = bih0[j0 + c] + bhh0[j0 + c];
        #pragma unroll
        for (int rr = 0; rr < 4; rr++) {
            acc[rr][0] = pack22(bv[0], bv[1]); acc[rr][1] = pack22(bv[2], bv[3]);
            acc[rr][2] = pack22(bv[4], bv[5]); acc[rr][3] = pack22(bv[6], bv[7]);
        }
    }

    #pragma unroll 4
    for (int k = 0; k < Iq; k++) {
        float4 h4 = *(const float4*)(sxT + k * 64 + r0);
        const ulonglong2* wp = (const ulonglong2*)(sW + k * Hq + j0);
        ulonglong2 wa = wp[0], wb = wp[1];
        u64 h0 = pack2(h4.x), h1 = pack2(h4.y), h2 = pack2(h4.z), h3 = pack2(h4.w);
        ffma2(acc[0][0], h0, wa.x); ffma2(acc[0][1], h0, wa.y);
        ffma2(acc[0][2], h0, wb.x); ffma2(acc[0][3], h0, wb.y);
        ffma2(acc[1][0], h1, wa.x); ffma2(acc[1][1], h1, wa.y);
        ffma2(acc[1][2], h1, wb.x); ffma2(acc[1][3], h1, wb.y);
        ffma2(acc[2][0], h2, wa.x); ffma2(acc[2][1], h2, wa.y);
        ffma2(acc[2][2], h2, wb.x); ffma2(acc[2][3], h2, wb.y);
        ffma2(acc[3][0], h3, wa.x); ffma2(acc[3][1], h3, wa.y);
        ffma2(acc[3][2], h3, wb.x); ffma2(acc[3][3], h3, wb.y);
    }

    #pragma unroll
    for (int rr = 0; rr < 4; rr++) {
        float o[8];
        unpack2(acc[rr][0], o[0], o[1]); unpack2(acc[rr][1], o[2], o[3]);
        unpack2(acc[rr][2], o[4], o[5]); unpack2(acc[rr][3], o[6], o[7]);
        float* p = &sxw[(r0 + rr) * 132 + j0];
        *(float4*)(p)     = make_float4(o[0], o[1], o[2], o[3]);
        *(float4*)(p + 4) = make_float4(o[4], o[5], o[6], o[7]);
    }
    __syncthreads();

    // remap to fragment layout, coalesced float4 stores
    float4* dst = (float4*)g_xw0;
    for (int w = tid; w < 2048; w += 256) {
        int gwp = w >> 9, nt = (w >> 5) & 15, lane = w & 31;
        int g = lane >> 2, p = lane & 3;
        int c0 = nt * 8 + p * 2;
        int ra = gwp * 16 + g, rb = ra + 8;
        float4 o = make_float4(sxw[ra * 132 + c0], sxw[ra * 132 + c0 + 1],
                               sxw[rb * 132 + c0], sxw[rb * 132 + c0 + 1]);
        size_t gw = (size_t)bblk * 4 + gwp;
        dst[(((size_t)t * 512 + gw) * 16 + nt) * 32 + lane] = o;
    }
}

// ================= kernel 2: fused 2-layer recurrence (HMMA) + FC =================
// dyn smem layout (bytes):
//   0                : 6 W tiles (order: W0h, W0l, Wih1h, Wih1l, Whh1h, Whh1l), 6*34816
//   208896           : b1 frag  float2[16][32]
//   212992           : fcw      float[10][128]
//   218112           : fcb      float[10]
#define OFF_B1F 208896
#define OFF_FCW 212992
#define OFF_FCB 218112
#define SMEM_DYN 218624

__global__ void __launch_bounds__(128, 1) rnn_main(
    const float* __restrict__ W_hh0, const float* __restrict__ W_ih1,
    const float* __restrict__ W_hh1, const float* __restrict__ b_ih1,
    const float* __restrict__ b_hh1, const float* __restrict__ fc_w,
    const float* __restrict__ fc_b, float* __restrict__ out)
{
    extern __shared__ char dyn[];
    const int tid = threadIdx.x;
    const int wid = tid >> 5, lane = tid & 31;
    const size_t gw = (size_t)blockIdx.x * 4 + wid;

    // ---- fill W tiles (fp32 -> bf16 hi/lo, padded rows) ----
    {
        const float* Ws[3] = { W_hh0, W_ih1, W_hh1 };
        #pragma unroll
        for (int m = 0; m < 3; m++) {
            __nv_bfloat16* dh = (__nv_bfloat16*)(dyn + (2 * m) * WTILE);
            __nv_bfloat16* dl = (__nv_bfloat16*)(dyn + (2 * m + 1) * WTILE);
            const float* W = Ws[m];
            for (int i = tid; i < Hq * Hq; i += 128) {
                int j = i >> 7, k = i & 127;
                float v = W[i];
                __nv_bfloat16 hb = __float2bfloat16(v);
                float lf = v - __bfloat162float(hb);
                dh[j * 136 + k] = hb;
                dl[j * 136 + k] = __float2bfloat16(lf);
            }
        }
    }
    float2* b1f = (float2*)(dyn + OFF_B1F);
    float*  fcw = (float*)(dyn + OFF_FCW);
    float*  fcb = (float*)(dyn + OFF_FCB);
    for (int i = tid; i < 512; i += 128) {
        int nt = i >> 5, l = i & 31, p = l & 3, j = nt * 8 + 2 * p;
        b1f[i] = make_float2(b_ih1[j] + b_hh1[j], b_ih1[j + 1] + b_hh1[j + 1]);
    }
    for (int i = tid; i < Cq * Hq; i += 128) fcw[i] = fc_w[i];
    if (tid < Cq) fcb[tid] = fc_b[tid];
    __syncthreads();

    const u32 smb = smem_u32(dyn);
    const u32 lmrow = (u32)(((((lane >> 4) & 1) * 8 + (lane & 7)) * WROW) + (((lane >> 3) & 1) * 16));
    const u32 W0H = smb,              W0L = smb + WTILE;
    const u32 WIH = smb + 2 * WTILE,  WIL = smb + 3 * WTILE;
    const u32 WHH = smb + 4 * WTILE,  WHL = smb + 5 * WTILE;

    u32 h0h[8][4], h0l[8][4], h1h[8][4], h1l[8][4];
    float D[16][4];

    const float4* xsrc = (const float4*)g_xw0;

    for (int t = 0; t < Tq; t++) {
        // ---- D init from xw frags (coalesced) ----
        {
            const float4* xp = xsrc + (((size_t)t * 512 + gw) * 16) * 32 + lane;
            #pragma unroll
            for (int nt = 0; nt < 16; nt++) {
                float4 v = xp[nt * 32];
                D[nt][0] = v.x; D[nt][1] = v.y; D[nt][2] = v.z; D[nt][3] = v.w;
            }
        }
        if (t > 0) gemm3(D, h0h, h0l, W0H, W0L, lmrow);

        // ---- epilogue 0 -> h0 frags ----
        #pragma unroll
        for (int kt = 0; kt < 8; kt++) {
            #pragma unroll
            for (int o = 0; o < 2; o++) {
                int nt = 2 * kt + o;
                float v0 = tanh_fast(D[nt][0]);
                float v1 = tanh_fast(D[nt][1]);
                float v2 = tanh_fast(D[nt][2]);
                float v3 = tanh_fast(D[nt][3]);
                u32 p01 = pack_bf16x2(v0, v1);
                u32 p23 = pack_bf16x2(v2, v3);
                h0h[kt][2 * o]     = p01;
                h0h[kt][2 * o + 1] = p23;
                h0l[kt][2 * o]     = pack_bf16x2(v0 - lo16f(p01), v1 - hi16f(p01));
                h0l[kt][2 * o + 1] = pack_bf16x2(v2 - lo16f(p23), v3 - hi16f(p23));
            }
        }

        // ---- layer 1: D = b1 + h1@Whh1^T + h0@Wih1^T ----
        #pragma unroll
        for (int nt = 0; nt < 16; nt++) {
            float2 bv = b1f[nt * 32 + lane];
            D[nt][0] = bv.x; D[nt][1] = bv.y; D[nt][2] = bv.x; D[nt][3] = bv.y;
        }
        if (t > 0) gemm3(D, h1h, h1l, WHH, WHL, lmrow);
        gemm3(D, h0h, h0l, WIH, WIL, lmrow);

        // ---- epilogue 1 -> h1 frags (last step keeps tanh'd values in D) ----
        if (t < Tq - 1) {
            #pragma unroll
            for (int kt = 0; kt < 8; kt++) {
                #pragma unroll
                for (int o = 0; o < 2; o++) {
                    int nt = 2 * kt + o;
                    float v0 = tanh_fast(D[nt][0]);
                    float v1 = tanh_fast(D[nt][1]);
                    float v2 = tanh_fast(D[nt][2]);
                    float v3 = tanh_fast(D[nt][3]);
                    u32 p01 = pack_bf16x2(v0, v1);
                    u32 p23 = pack_bf16x2(v2, v3);
                    h1h[kt][2 * o]     = p01;
                    h1h[kt][2 * o + 1] = p23;
                    h1l[kt][2 * o]     = pack_bf16x2(v0 - lo16f(p01), v1 - hi16f(p01));
                    h1l[kt][2 * o + 1] = pack_bf16x2(v2 - lo16f(p23), v3 - hi16f(p23));
                }
            }
        } else {
            #pragma unroll
            for (int nt = 0; nt < 16; nt++) {
                #pragma unroll
                for (int q = 0; q < 4; q++) D[nt][q] = tanh_fast(D[nt][q]);
            }
        }
    }

    // ---- FC epilogue ----
    __syncthreads();                    // W tiles no longer needed by anyone
    float* stg = (float*)(dyn + wid * 8448);   // [16 rows][132] per warp
    {
        int g = lane >> 2, p = lane & 3;
        #pragma unroll
        for (int nt = 0; nt < 16; nt++) {
            int j = nt * 8 + p * 2;
            stg[g * 132 + j]           = D[nt][0];
            stg[g * 132 + j + 1]       = D[nt][1];
            stg[(g + 8) * 132 + j]     = D[nt][2];
            stg[(g + 8) * 132 + j + 1] = D[nt][3];
        }
    }
    __syncwarp();
    {
        int row = lane & 15, half = lane >> 4;
        float acc[Cq];
        #pragma unroll
        for (int c = 0; c < Cq; c++) acc[c] = half ? 0.0f : fcb[c];
        const float* hv = stg + row * 132 + half * 64;
        const float* fw = fcw + half * 64;
        #pragma unroll 4
        for (int k = 0; k < 64; k++) {
            float h = hv[k];
            #pragma unroll
            for (int c = 0; c < Cq; c++)
                acc[c] = fmaf(h, fw[c * Hq + k], acc[c]);
        }
        #pragma unroll
        for (int c = 0; c < Cq; c++) acc[c] += __shfl_xor_sync(0xFFFFFFFFu, acc[c], 16);
        if (lane < 16) {
            size_t b = gw * 16 + row;
            #pragma unroll
            for (int c = 0; c < Cq; c++) out[b * Cq + c] = acc[c];
        }
    }
}

// ================= host entry =================
extern "C" void kernel_launch(void* const* d_in, const int* in_sizes, int n_in,
                              void* d_out, int out_size) {
    const float* x     = (const float*)d_in[0];
    const float* W_ih0 = (const float*)d_in[1];
    const float* W_hh0 = (const float*)d_in[2];
    const float* b_ih0 = (const float*)d_in[3];
    const float* b_hh0 = (const float*)d_in[4];
    const float* W_ih1 = (const float*)d_in[5];
    const float* W_hh1 = (const float*)d_in[6];
    const float* b_ih1 = (const float*)d_in[7];
    const float* b_hh1 = (const float*)d_in[8];
    const float* fc_w  = (const float*)d_in[9];
    const float* fc_b  = (const float*)d_in[10];
    float* out = (float*)d_out;

    cudaFuncSetAttribute(rnn_main, cudaFuncAttributeMaxDynamicSharedMemorySize, SMEM_DYN);

    xw_kernel<<<Tq * 128, 256>>>(x, W_ih0, b_ih0, b_hh0);
    rnn_main<<<128, 128, SMEM_DYN>>>(W_hh0, W_ih1, W_hh1, b_ih1, b_hh1, fc_w, fc_b, out);
}

// round 9
// speedup vs baseline: 4.4084x; 1.5896x over previous
#include <cuda_runtime.h>
#include <cuda_bf16.h>

typedef unsigned int u32;

#define Tq 28
#define Iq 28
#define Hq 128
#define Cq 10

// SMEM map (bytes): W0h@0 W0l@32768 WIh@65536 WIl@98304 WHh@131072 WHl@163840 (256B-row swizzle)
// X0h@196608 X0l@204800 (64B-row swizzle) | exch@212992(16K; FC reuse: fcw@212992 part@218112)
// b0@229376 b1@229888
#define OFF_X0H 196608
#define OFF_X0L 204800
#define OFF_EX  212992
#define OFF_PART 218112
#define OFF_B0 229376
#define OFF_B1 229888
#define SMEM_DYN 230400

static __device__ __forceinline__ u32 smem_u32(const void* p) {
    u32 a; asm("{ .reg .u64 t; cvta.to.shared.u64 t, %1; cvt.u32.u64 %0, t; }" : "=r"(a) : "l"(p));
    return a;
}
static __device__ __forceinline__ float tanh_fast(float x) {
    float ax = fabsf(x), e = __expf(-2.f * ax);
    return copysignf(__fdividef(1.f - e, 1.f + e), x);
}
static __device__ __forceinline__ u32 pack_bf16x2(float lo, float hi) {
    u32 r; asm("cvt.rn.bf16x2.f32 %0, %1, %2;" : "=r"(r) : "f"(hi), "f"(lo)); return r;
}
static __device__ __forceinline__ float lo16f(u32 p) { return __uint_as_float(p << 16); }
static __device__ __forceinline__ float hi16f(u32 p) { return __uint_as_float(p & 0xFFFF0000u); }

static __device__ __forceinline__ void mma_bf16(float (&d)[4], const u32 (&a)[4], u32 b0, u32 b1) {
    asm volatile(
        "mma.sync.aligned.m16n8k16.row.col.f32.bf16.bf16.f32 "
        "{%0,%1,%2,%3}, {%4,%5,%6,%7}, {%8,%9}, {%0,%1,%2,%3};"
        : "+f"(d[0]), "+f"(d[1]), "+f"(d[2]), "+f"(d[3])
        : "r"(a[0]), "r"(a[1]), "r"(a[2]), "r"(a[3]), "r"(b0), "r"(b1));
}
#define LDMX4(r0, r1, r2, r3, addr) \
    asm volatile("ldmatrix.sync.aligned.m8n8.x4.shared.b16 {%0,%1,%2,%3}, [%4];" \
        : "=r"(r0), "=r"(r1), "=r"(r2), "=r"(r3) : "r"(addr))
#define STS128(addr, r) \
    asm volatile("st.shared.v4.b32 [%0], {%1,%2,%3,%4};" \
        :: "r"(addr), "r"((r)[0]), "r"((r)[1]), "r"((r)[2]), "r"((r)[3]) : "memory")
#define LDS128(r, addr) \
    asm volatile("ld.shared.v4.b32 {%0,%1,%2,%3}, [%4];" \
        : "=r"((r)[0]), "=r"((r)[1]), "=r"((r)[2]), "=r"((r)[3]) : "r"(addr) : "memory")
#define BARS(id) asm volatile("bar.sync %0, 64;" :: "r"(id) : "memory")

// D[8][4] += A(hi,lo) @ W(hi,lo)^T over this warp's 64 j-cols. 256B-row swizzled tile.
static __device__ __forceinline__ void gemm3h(float (&D)[8][4],
                                              const u32 (&Ah)[8][4], const u32 (&Al)[8][4],
                                              u32 whb, u32 wlb, u32 hsR, u32 sw56)
{
    #pragma unroll
    for (int kt = 0; kt < 8; kt++) {
        u32 cx = ((u32)(kt * 32) ^ sw56) + hsR;
        #pragma unroll
        for (int np = 0; np < 4; np++) {
            u32 off = (u32)(np * 4096) + cx;
            u32 bh0, bh1, bh2, bh3, bl0, bl1, bl2, bl3;
            LDMX4(bh0, bh1, bh2, bh3, whb + off);
            LDMX4(bl0, bl1, bl2, bl3, wlb + off);
            mma_bf16(D[2 * np],     Ah[kt], bh0, bh1);
            mma_bf16(D[2 * np],     Al[kt], bh0, bh1);
            mma_bf16(D[2 * np],     Ah[kt], bl0, bl1);
            mma_bf16(D[2 * np + 1], Ah[kt], bh2, bh3);
            mma_bf16(D[2 * np + 1], Al[kt], bh2, bh3);
            mma_bf16(D[2 * np + 1], Ah[kt], bl2, bl3);
        }
    }
}
// x GEMM: K=32 (2 chunks), 64B-row swizzled X tile.
static __device__ __forceinline__ void gemm_x(float (&D)[8][4],
                                              const u32 (&Ah)[2][4], const u32 (&Al)[2][4],
                                              u32 xhb, u32 xlb, u32 hsX, u32 sw5x)
{
    #pragma unroll
    for (int kt = 0; kt < 2; kt++) {
        u32 cx = ((u32)(kt * 32) ^ sw5x) + hsX;
        #pragma unroll
        for (int np = 0; np < 4; np++) {
            u32 off = (u32)(np * 1024) + cx;
            u32 bh0, bh1, bh2, bh3, bl0, bl1, bl2, bl3;
            LDMX4(bh0, bh1, bh2, bh3, xhb + off);
            LDMX4(bl0, bl1, bl2, bl3, xlb + off);
            mma_bf16(D[2 * np],     Ah[kt], bh0, bh1);
            mma_bf16(D[2 * np],     Al[kt], bh0, bh1);
            mma_bf16(D[2 * np],     Ah[kt], bl0, bl1);
            mma_bf16(D[2 * np + 1], Ah[kt], bh2, bh3);
            mma_bf16(D[2 * np + 1], Al[kt], bh2, bh3);
            mma_bf16(D[2 * np + 1], Ah[kt], bl2, bl3);
        }
    }
}
// tanh epilogue: D (own 64 cols) -> hi/lo A-frag chunks [base..base+3]
static __device__ __forceinline__ void tanh_pack(const float (&D)[8][4],
                                                 u32 (&hh)[8][4], u32 (&hl)[8][4], int base)
{
    #pragma unroll
    for (int ktl = 0; ktl < 4; ktl++) {
        #pragma unroll
        for (int o = 0; o < 2; o++) {
            int nt = 2 * ktl + o;
            float v0 = tanh_fast(D[nt][0]), v1 = tanh_fast(D[nt][1]);
            float v2 = tanh_fast(D[nt][2]), v3 = tanh_fast(D[nt][3]);
            u32 p01 = pack_bf16x2(v0, v1), p23 = pack_bf16x2(v2, v3);
            hh[base + ktl][2 * o] = p01;  hh[base + ktl][2 * o + 1] = p23;
            hl[base + ktl][2 * o]     = pack_bf16x2(v0 - lo16f(p01), v1 - hi16f(p01));
            hl[base + ktl][2 * o + 1] = pack_bf16x2(v2 - lo16f(p23), v3 - hi16f(p23));
        }
    }
}
// pairwise hi/lo fragment exchange through SMEM (own chunks -> partner's missing chunks)
static __device__ __forceinline__ void xchg(u32 (&hh)[8][4], u32 (&hl)[8][4],
                                            u32 exOwn, u32 exOth, int own, int oth, int barid)
{
    #pragma unroll
    for (int k = 0; k < 4; k++) STS128(exOwn + k * 512, hh[own + k]);
    BARS(barid);
    #pragma unroll
    for (int k = 0; k < 4; k++) LDS128(hh[oth + k], exOth + k * 512);
    BARS(barid);
    #pragma unroll
    for (int k = 0; k < 4; k++) STS128(exOwn + k * 512, hl[own + k]);
    BARS(barid);
    #pragma unroll
    for (int k = 0; k < 4; k++) LDS128(hl[oth + k], exOth + k * 512);
    BARS(barid);
}

__global__ void __launch_bounds__(256, 1) rnn_fused(
    const float* __restrict__ x,
    const float* __restrict__ W_ih0, const float* __restrict__ W_hh0,
    const float* __restrict__ b_ih0, const float* __restrict__ b_hh0,
    const float* __restrict__ W_ih1, const float* __restrict__ W_hh1,
    const float* __restrict__ b_ih1, const float* __restrict__ b_hh1,
    const float* __restrict__ fc_w,  const float* __restrict__ fc_b,
    float* __restrict__ out)
{
    extern __shared__ char dyn[];
    const int tid = threadIdx.x;
    const int wid = tid >> 5, lane = tid & 31;
    const int rg = wid & 3, jh = wid >> 2;     // row-group 0..3, j-half 0..1
    const int g = lane >> 2, p = lane & 3;

    // ---- init: W tiles bf16 hi/lo, swizzled ----
    {
        const float* Ws[3] = { W_hh0, W_ih1, W_hh1 };
        #pragma unroll
        for (int m = 0; m < 3; m++) {
            char* dh = dyn + (2 * m) * 32768;
            char* dl = dyn + (2 * m + 1) * 32768;
            const float* W = Ws[m];
            for (int i = tid; i < Hq * Hq; i += 256) {
                int j = i >> 7, k = i & 127;
                float v = W[i];
                __nv_bfloat16 hb = __float2bfloat16(v);
                u32 a = (u32)(j * 256) + (u32)((2 * k) ^ ((j & 7) << 4));
                *(__nv_bfloat16*)(dh + a) = hb;
                *(__nv_bfloat16*)(dl + a) = __float2bfloat16(v - __bfloat162float(hb));
            }
        }
        for (int i = tid; i < Hq * 32; i += 256) {   // X tiles [j][k pad32]
            int j = i >> 5, k = i & 31;
            float v = (k < Iq) ? W_ih0[j * Iq + k] : 0.0f;
            __nv_bfloat16 hb = __float2bfloat16(v);
            u32 a = (u32)(j * 64) + (u32)((2 * k) ^ ((j & 3) << 4));
            *(__nv_bfloat16*)(dyn + OFF_X0H + a) = hb;
            *(__nv_bfloat16*)(dyn + OFF_X0L + a) = __float2bfloat16(v - __bfloat162float(hb));
        }
        float* b0s = (float*)(dyn + OFF_B0);
        float* b1s = (float*)(dyn + OFF_B1);
        for (int i = tid; i < Hq; i += 256) {
            b0s[i] = b_ih0[i] + b_hh0[i];
            b1s[i] = b_ih1[i] + b_hh1[i];
        }
    }
    __syncthreads();

    const u32 smb = smem_u32(dyn);
    const u32 r    = (u32)((((lane >> 4) & 1) * 8) + (lane & 7));    // ldmatrix row 0..15
    const u32 h16  = (u32)(((lane >> 3) & 1) * 16);                  // k chunk 0/+8
    const u32 swzR = (u32)((lane & 7) << 4);
    const u32 hsR  = r * 256 + (h16 ^ (swzR & 16));
    const u32 sw56 = swzR & 96;
    const u32 swzX = (u32)((lane & 3) << 4);
    const u32 hsX  = r * 64 + (h16 ^ (swzX & 16));
    const u32 sw5x = swzX & 32;

    const u32 W0H = smb + (u32)(jh * 16384),           W0L = smb + 32768  + (u32)(jh * 16384);
    const u32 WIH = smb + 65536 + (u32)(jh * 16384),   WIL = smb + 98304  + (u32)(jh * 16384);
    const u32 WHH = smb + 131072 + (u32)(jh * 16384),  WHL = smb + 163840 + (u32)(jh * 16384);
    const u32 X0H = smb + OFF_X0H + (u32)(jh * 4096),  X0L = smb + OFF_X0L + (u32)(jh * 4096);
    const u32 exOwn = smb + OFF_EX + (u32)((((rg * 2 + jh) * 4) * 32 + lane) * 16);
    const u32 exOth = smb + OFF_EX + (u32)((((rg * 2 + 1 - jh) * 4) * 32 + lane) * 16);
    const int own = jh * 4, oth = (1 - jh) * 4, barid = rg + 1;

    const float* b0s = (float*)(dyn + OFF_B0);
    const float* b1s = (float*)(dyn + OFF_B1);
    const size_t rowA = ((size_t)blockIdx.x * 4 + rg) * 16 + g;
    const float* xA = x + rowA * Tq * Iq;
    const float* xB = x + (rowA + 8) * Tq * Iq;

    u32 h0h[8][4], h0l[8][4], h1h[8][4], h1l[8][4];
    float D[8][4];

    for (int t = 0; t < Tq; t++) {
        // x A-frags (K=32, rows g/g+8)
        u32 xh[2][4], xl[2][4];
        {
            const float* at = xA + t * Iq;
            const float* bt = xB + t * Iq;
            float2 xv[8];
            xv[0] = *(const float2*)(at + 2 * p);       xv[1] = *(const float2*)(bt + 2 * p);
            xv[2] = *(const float2*)(at + 8 + 2 * p);   xv[3] = *(const float2*)(bt + 8 + 2 * p);
            xv[4] = *(const float2*)(at + 16 + 2 * p);  xv[5] = *(const float2*)(bt + 16 + 2 * p);
            xv[6] = (p < 2) ? *(const float2*)(at + 24 + 2 * p) : make_float2(0.f, 0.f);
            xv[7] = (p < 2) ? *(const float2*)(bt + 24 + 2 * p) : make_float2(0.f, 0.f);
            #pragma unroll
            for (int q = 0; q < 8; q++) {
                u32 hu = pack_bf16x2(xv[q].x, xv[q].y);
                xh[q >> 2][q & 3] = hu;
                xl[q >> 2][q & 3] = pack_bf16x2(xv[q].x - lo16f(hu), xv[q].y - hi16f(hu));
            }
        }

        // layer 0: D = b0 + h0@W0^T + x@Wih0^T
        #pragma unroll
        for (int nt = 0; nt < 8; nt++) {
            float2 bv = *(const float2*)&b0s[jh * 64 + nt * 8 + p * 2];
            D[nt][0] = bv.x; D[nt][1] = bv.y; D[nt][2] = bv.x; D[nt][3] = bv.y;
        }
        if (t > 0) gemm3h(D, h0h, h0l, W0H, W0L, hsR, sw56);
        gemm_x(D, xh, xl, X0H, X0L, hsX, sw5x);
        tanh_pack(D, h0h, h0l, own);
        xchg(h0h, h0l, exOwn, exOth, own, oth, barid);

        // layer 1: D = b1 + h1@Whh1^T + h0@Wih1^T
        #pragma unroll
        for (int nt = 0; nt < 8; nt++) {
            float2 bv = *(const float2*)&b1s[jh * 64 + nt * 8 + p * 2];
            D[nt][0] = bv.x; D[nt][1] = bv.y; D[nt][2] = bv.x; D[nt][3] = bv.y;
        }
        if (t > 0) gemm3h(D, h1h, h1l, WHH, WHL, hsR, sw56);
        gemm3h(D, h0h, h0l, WIH, WIL, hsR, sw56);
        if (t < Tq - 1) {
            tanh_pack(D, h1h, h1l, own);
            xchg(h1h, h1l, exOwn, exOth, own, oth, barid);
        } else {
            #pragma unroll
            for (int nt = 0; nt < 8; nt++)
                #pragma unroll
                for (int q = 0; q < 4; q++) D[nt][q] = tanh_fast(D[nt][q]);
        }
    }

    // ---- FC: out = h1 @ fc_w^T + fc_b ----
    __syncthreads();
    float* fcs  = (float*)(dyn + OFF_EX);
    float* part = (float*)(dyn + OFF_PART);
    for (int i = tid; i < Cq * Hq; i += 256) fcs[i] = fc_w[i];
    __syncthreads();

    float accA[Cq], accB[Cq];
    #pragma unroll
    for (int c = 0; c < Cq; c++) { accA[c] = 0.f; accB[c] = 0.f; }
    #pragma unroll
    for (int nt = 0; nt < 8; nt++) {
        int j = jh * 64 + nt * 8 + p * 2;
        #pragma unroll
        for (int c = 0; c < Cq; c++) {
            float2 fw = *(const float2*)&fcs[c * Hq + j];
            accA[c] = fmaf(D[nt][0], fw.x, fmaf(D[nt][1], fw.y, accA[c]));
            accB[c] = fmaf(D[nt][2], fw.x, fmaf(D[nt][3], fw.y, accB[c]));
        }
    }
    #pragma unroll
    for (int c = 0; c < Cq; c++) {
        accA[c] += __shfl_xor_sync(0xFFFFFFFFu, accA[c], 1);
        accA[c] += __shfl_xor_sync(0xFFFFFFFFu, accA[c], 2);
        accB[c] += __shfl_xor_sync(0xFFFFFFFFu, accB[c], 1);
        accB[c] += __shfl_xor_sync(0xFFFFFFFFu, accB[c], 2);
    }
    if (p == 0) {
        int base = (rg * 2 + jh) * 16;
        #pragma unroll
        for (int c = 0; c < Cq; c++) {
            part[(base + g) * Cq + c]     = accA[c];
            part[(base + g + 8) * Cq + c] = accB[c];
        }
    }
    __syncthreads();
    for (int i = tid; i < 64 * Cq; i += 256) {
        int row = i / Cq, c = i - row * Cq;
        int rg2 = row >> 4, rr = row & 15;
        float v = fc_b[c] + part[((rg2 * 2) * 16 + rr) * Cq + c]
                          + part[((rg2 * 2 + 1) * 16 + rr) * Cq + c];
        out[((size_t)blockIdx.x * 64 + row) * Cq + c] = v;
    }
}

extern "C" void kernel_launch(void* const* d_in, const int* in_sizes, int n_in,
                              void* d_out, int out_size) {
    const float* x     = (const float*)d_in[0];
    const float* W_ih0 = (const float*)d_in[1];
    const float* W_hh0 = (const float*)d_in[2];
    const float* b_ih0 = (const float*)d_in[3];
    const float* b_hh0 = (const float*)d_in[4];
    const float* W_ih1 = (const float*)d_in[5];
    const float* W_hh1 = (const float*)d_in[6];
    const float* b_ih1 = (const float*)d_in[7];
    const float* b_hh1 = (const float*)d_in[8];
    const float* fc_w  = (const float*)d_in[9];
    const float* fc_b  = (const float*)d_in[10];
    float* out = (float*)d_out;

    cudaFuncSetAttribute(rnn_fused, cudaFuncAttributeMaxDynamicSharedMemorySize, SMEM_DYN);
    rnn_fused<<<128, 256, SMEM_DYN>>>(x, W_ih0, W_hh0, b_ih0, b_hh0,
                                      W_ih1, W_hh1, b_ih1, b_hh1, fc_w, fc_b, out);
}